// round 15
// baseline (speedup 1.0000x reference)
#include <cuda_runtime.h>

// Problem constants (fixed by setup_inputs): B=8, N=16384, K=64
#define BB    8
#define NN    16384
#define KK    64
#define MTOT  (BB * NN)            // 131072 points total
#define NROWS (BB * KK)            // 512 (b,k) rows
#define NHALF (NROWS * 2)          // 1024 half-row BN units
// inv = -1/(2*sigma^2) = -12.5 ;  C = inv * log2(e)
#define CLOG2 (-18.033688011112043f)

#define GRID  444                  // 3 CTAs/SM on 148 SMs, all co-resident
#define TPB   256                  // 8 warps
#define PTS_A 32
#define NUNITA (MTOT / PTS_A)      // 4096 stage-A warp units
#define PTS_B 16
#define NUNITB (MTOT / PTS_B)      // 8192 stage-B warp units

// Scratch (no cudaMalloc allowed)
__device__ float  g_h[(size_t)MTOT * KK];   // 33.5 MB: h[b][j][k], k contiguous
__device__ double g_sum[KK];
__device__ double g_ssum[KK];
__device__ unsigned g_workA;
__device__ unsigned g_workB;
__device__ unsigned g_arrive;               // grid barrier, monotonic across replays
__device__ volatile unsigned g_release;

__device__ __forceinline__ float ex2f(float x) {
    float r;
    asm("ex2.approx.ftz.f32 %0, %1;" : "=f"(r) : "f"(x));
    return r;
}

// Software grid barrier. Monotonic epoch counters -> safe across graph replays.
__device__ __forceinline__ void gsync() {
    __syncthreads();
    if (threadIdx.x == 0) {
        __threadfence();
        unsigned t = atomicAdd(&g_arrive, 1u);
        unsigned ep = t / GRID + 1u;
        if (t % GRID == GRID - 1u) {
            g_release = ep;
        } else {
            while (g_release < ep) { __nanosleep(64); }
        }
        __threadfence();
    }
    __syncthreads();
}

__global__ void __launch_bounds__(TPB, 3) fkc_fused(
    const float* __restrict__ normals,
    const void*  __restrict__ nidx,
    const float* __restrict__ wa,
    const float* __restrict__ wb,
    const float* __restrict__ gamma,
    const float* __restrict__ beta,
    float* __restrict__ out)
{
    __shared__ float sT[8][PTS_B * 66];   // per-warp transpose tiles (33.8 KB)
    __shared__ int   sIdx32;

    const int tid  = threadIdx.x;
    const int warp = tid >> 5;
    const int lane = tid & 31;
    float* sTw = sT[warp];

    if (tid == 0) {
        // Probe int32 (JAX default) vs int64 neighbor_idx
        int is32 = 0;
        const long long* p = (const long long*)nidx;
        for (int j = 0; j < 8; j++) {
            long long v = p[j];
            if (v < 0 || v >= NN) is32 = 1;
        }
        sIdx32 = is32;
    }
    if (blockIdx.x == 0 && tid < KK) { g_sum[tid] = 0.0; g_ssum[tid] = 0.0; }

    // Per-lane weights: k = lane (low half) and k = lane+32 (high half)
    // w' = -2C * w ; we = exp2(C*||w||^2)/16
    float WxL[4], WyL[4], WzL[4], WeL[4];
    float WxH[4], WyH[4], WzH[4], WeH[4];
#pragma unroll
    for (int m = 0; m < 4; m++) {
#pragma unroll
        for (int half = 0; half < 2; half++) {
            int k = lane + half * 32;
            float a = __ldg(wa + k * 4 + m), b = __ldg(wb + k * 4 + m);
            float sa, ca, sb, cb;
            sincosf(a, &sa, &ca);
            sincosf(b, &sb, &cb);
            float wx = sa * cb, wy = sa * sb, wz = ca;
            float W2 = wx * wx + wy * wy + wz * wz;
            const float s = -2.0f * CLOG2;
            float we = exp2f(CLOG2 * W2) * (1.0f / 16.0f);
            if (half == 0) { WxL[m] = wx * s; WyL[m] = wy * s; WzL[m] = wz * s; WeL[m] = we; }
            else           { WxH[m] = wx * s; WyH[m] = wy * s; WzH[m] = wz * s; WeH[m] = we; }
        }
    }
    __syncthreads();
    const int idx32 = sIdx32;

    // ---- Stage A: h[b][j][k] = sum_m exp2(f.w'_km + C||f||^2) * we_km ----
    // Warp-autonomous work stealing; lane = k / k+32.
    for (;;) {
        unsigned u;
        if (lane == 0) u = atomicAdd(&g_workA, 1u);
        u = __shfl_sync(0xFFFFFFFFu, u, 0);
        if (u >= NUNITA) break;

        int base = (int)u * PTS_A;
        int b  = base >> 14;
        int n0 = base & (NN - 1);
        const float* nb = normals + (size_t)b * (3 * NN);
        float* hp = g_h + ((size_t)b * NN + n0) * KK + lane;

#pragma unroll 4
        for (int p = 0; p < PTS_A; p++) {
            int n = n0 + p;
            float x = __ldg(nb + n);
            float y = __ldg(nb + NN + n);
            float z = __ldg(nb + 2 * NN + n);
            float cf2 = CLOG2 * fmaf(x, x, fmaf(y, y, z * z));
            float slo = 0.f, shi = 0.f;
#pragma unroll
            for (int m = 0; m < 4; m++) {
                slo = fmaf(ex2f(fmaf(x, WxL[m], fmaf(y, WyL[m], fmaf(z, WzL[m], cf2)))), WeL[m], slo);
                shi = fmaf(ex2f(fmaf(x, WxH[m], fmaf(y, WyH[m], fmaf(z, WzH[m], cf2)))), WeH[m], shi);
            }
            hp[(size_t)p * KK]      = slo;
            hp[(size_t)p * KK + 32] = shi;
        }
    }

    gsync();   // all h written, stats zeroed
    if (blockIdx.x == 0 && tid == 0) g_workA = 0;   // reset for next replay

    // ---- Stage B: feat = gather-sum of 4 h rows; transpose-write + stats --
    // Warp-autonomous; lane = k / k+32; per-warp smem tile; no __syncthreads.
    float s_lo = 0.f, ss_lo = 0.f, s_hi = 0.f, ss_hi = 0.f;
    for (;;) {
        unsigned u;
        if (lane == 0) u = atomicAdd(&g_workB, 1u);
        u = __shfl_sync(0xFFFFFFFFu, u, 0);
        if (u >= NUNITB) break;

        int base = (int)u * PTS_B;
        int b  = base >> 14;
        int n0 = base & (NN - 1);
        const float* hb = g_h + (size_t)b * NN * KK;

        // Neighbor triples for the 16 points live in lanes 0..15 (dup in 16..31)
        int j1, j2, j3;
        {
            int il = lane & 15;
            size_t rowbase = ((size_t)b * NN + n0 + il) * 3;
            if (idx32) {
                const int* ip = (const int*)nidx + rowbase;
                j1 = ip[0]; j2 = ip[1]; j3 = ip[2];
            } else {
                const long long* ip = (const long long*)nidx + rowbase;
                j1 = (int)ip[0]; j2 = (int)ip[1]; j3 = (int)ip[2];
            }
        }

#pragma unroll
        for (int pt0 = 0; pt0 < PTS_B; pt0 += 4) {
            float L0[4], L1[4], L2[4], L3[4];
            float H0[4], H1[4], H2[4], H3[4];
#pragma unroll
            for (int q = 0; q < 4; q++) {
                int pt = pt0 + q;
                int a1 = __shfl_sync(0xFFFFFFFFu, j1, pt);
                int a2 = __shfl_sync(0xFFFFFFFFu, j2, pt);
                int a3 = __shfl_sync(0xFFFFFFFFu, j3, pt);
                const float* r0 = hb + (size_t)(n0 + pt) * KK + lane;
                const float* r1 = hb + (size_t)a1 * KK + lane;
                const float* r2 = hb + (size_t)a2 * KK + lane;
                const float* r3 = hb + (size_t)a3 * KK + lane;
                L0[q] = __ldg(r0);      L1[q] = __ldg(r1);
                L2[q] = __ldg(r2);      L3[q] = __ldg(r3);
                H0[q] = __ldg(r0 + 32); H1[q] = __ldg(r1 + 32);
                H2[q] = __ldg(r2 + 32); H3[q] = __ldg(r3 + 32);
            }
#pragma unroll
            for (int q = 0; q < 4; q++) {
                int pt = pt0 + q;
                float vlo = (L0[q] + L1[q]) + (L2[q] + L3[q]);
                float vhi = (H0[q] + H1[q]) + (H2[q] + H3[q]);
                sTw[pt * 66 + lane]      = vlo;
                sTw[pt * 66 + 32 + lane] = vhi;
                s_lo += vlo; ss_lo = fmaf(vlo, vlo, ss_lo);
                s_hi += vhi; ss_hi = fmaf(vhi, vhi, ss_hi);
            }
        }
        __syncwarp();

        // Transposed flush: lanes 0-15 row r, lanes 16-31 row r+1 (conflict-free
        // via stride-66 padding); stores are 64B-aligned 16-float runs.
        {
            int nn = lane & 15;
            int rh = lane >> 4;
            float* ob = out + (size_t)b * KK * NN + n0 + nn;
#pragma unroll
            for (int r2 = 0; r2 < KK; r2 += 2) {
                int r = r2 + rh;
                ob[(size_t)r * NN] = sTw[nn * 66 + r];
            }
        }
        __syncwarp();
    }

    // Per-warp stats flush: lane owns k=lane and k=lane+32
    atomicAdd(&g_sum[lane],       (double)s_lo);
    atomicAdd(&g_ssum[lane],      (double)ss_lo);
    atomicAdd(&g_sum[lane + 32],  (double)s_hi);
    atomicAdd(&g_ssum[lane + 32], (double)ss_hi);

    gsync();   // all stats accumulated
    if (blockIdx.x == 0 && tid == 0) g_workB = 0;   // reset for next replay

    // ---- Stage C: BN + ReLU in place (L2-resident) ------------------------
    for (int h = blockIdx.x; h < NHALF; h += GRID) {
        int r = h >> 1;
        int kk = r & (KK - 1);
        double mean = g_sum[kk] * (1.0 / MTOT);
        double var  = g_ssum[kk] * (1.0 / MTOT) - mean * mean;
        float sc = __ldg(gamma + kk) * rsqrtf((float)var + 1e-5f);
        float sh = __ldg(beta + kk) - (float)mean * sc;
        float4* p4 = (float4*)(out + (size_t)r * NN + (h & 1) * (NN / 2));
#pragma unroll
        for (int i = 0; i < NN / 8 / TPB; i++) {   // 8 iterations
            float4 v = p4[i * TPB + tid];
            v.x = fmaxf(fmaf(v.x, sc, sh), 0.f);
            v.y = fmaxf(fmaf(v.y, sc, sh), 0.f);
            v.z = fmaxf(fmaf(v.z, sc, sh), 0.f);
            v.w = fmaxf(fmaf(v.w, sc, sh), 0.f);
            p4[i * TPB + tid] = v;
        }
    }
}

extern "C" void kernel_launch(void* const* d_in, const int* in_sizes, int n_in,
                              void* d_out, int out_size) {
    const float* normals = (const float*)d_in[0];
    const void*  nidx    = d_in[1];
    const float* wa      = (const float*)d_in[2];
    const float* wb      = (const float*)d_in[3];
    const float* gamma   = (const float*)d_in[4];
    const float* beta    = (const float*)d_in[5];
    float* out = (float*)d_out;

    fkc_fused<<<GRID, TPB>>>(normals, nidx, wa, wb, gamma, beta, out);
}

// round 16
// speedup vs baseline: 1.6375x; 1.6375x over previous
#include <cuda_runtime.h>

// Problem constants (fixed by setup_inputs): B=8, N=16384, K=64
#define BB    8
#define NN    16384
#define KK    64
#define MTOT  (BB * NN)            // 131072 points total
#define NROWS (BB * KK)            // 512 (b,k) rows
#define NHALF (NROWS * 2)          // 1024 half-row BN units
// inv = -1/(2*sigma^2) = -12.5 ;  C = inv * log2(e)
#define CLOG2 (-18.033688011112043f)

#define GRID  444                  // 3 CTAs/SM on 148 SMs, all co-resident
#define TPB   256                  // 8 warps
#define PTS_W 32
#define NUNIT (MTOT / PTS_W)       // 4096 phase-1 warp units

// Scratch (no cudaMalloc allowed)
__device__ double g_sum[KK];
__device__ double g_ssum[KK];
__device__ unsigned g_work1;
__device__ unsigned g_work2;
__device__ unsigned g_arrive;              // grid barrier, monotonic across replays
__device__ volatile unsigned g_release;

typedef unsigned long long u64;

__device__ __forceinline__ float ex2f(float x) {
    float r;
    asm("ex2.approx.ftz.f32 %0, %1;" : "=f"(r) : "f"(x));
    return r;
}
__device__ __forceinline__ u64 pk2(float lo, float hi) {
    u64 r;
    asm("mov.b64 %0, {%1, %2};" : "=l"(r) : "f"(lo), "f"(hi));
    return r;
}
__device__ __forceinline__ void upk2(u64 v, float& a, float& b) {
    asm("mov.b64 {%0, %1}, %2;" : "=f"(a), "=f"(b) : "l"(v));
}
__device__ __forceinline__ u64 fma2(u64 a, u64 b, u64 c) {
    u64 d;
    asm("fma.rn.f32x2 %0, %1, %2, %3;" : "=l"(d) : "l"(a), "l"(b), "l"(c));
    return d;
}
__device__ __forceinline__ u64 mul2(u64 a, u64 b) {
    u64 d;
    asm("mul.rn.f32x2 %0, %1, %2;" : "=l"(d) : "l"(a), "l"(b));
    return d;
}
__device__ __forceinline__ u64 add2(u64 a, u64 b) {
    u64 d;
    asm("add.rn.f32x2 %0, %1, %2;" : "=l"(d) : "l"(a), "l"(b));
    return d;
}

// Packed polynomial exp2 for t in [-40, +40]: runs on FMA+ALU pipes, not MUFU.
// round-to-int via 1.5*2^23 magic; deg-5 Horner on f in [-0.5, 0.5]; 2^i via
// integer exponent construction. Rel err ~1e-6.
__device__ __forceinline__ u64 exp2poly2(u64 t) {
    const u64 MAG2 = pk2(12582912.0f, 12582912.0f);   // 1.5 * 2^23
    const u64 NEG1 = pk2(-1.0f, -1.0f);
    u64 r  = add2(t, MAG2);
    u64 rr = fma2(MAG2, NEG1, r);     // r - MAG (exact)
    u64 f  = fma2(rr, NEG1, t);       // t - round(t), in [-0.5, 0.5]
    unsigned i0, i1;
    asm("mov.b64 {%0, %1}, %2;" : "=r"(i0), "=r"(i1) : "l"(r));
    unsigned s0 = (i0 << 23) + 0x3F800000u;   // (n + 127) << 23 == 2^n bits
    unsigned s1 = (i1 << 23) + 0x3F800000u;
    u64 sc;
    asm("mov.b64 %0, {%1, %2};" : "=l"(sc) : "r"(s0), "r"(s1));
    u64 p = pk2(1.3333558146e-3f, 1.3333558146e-3f);
    p = fma2(p, f, pk2(9.6181291076e-3f, 9.6181291076e-3f));
    p = fma2(p, f, pk2(5.5504108664e-2f, 5.5504108664e-2f));
    p = fma2(p, f, pk2(2.4022650696e-1f, 2.4022650696e-1f));
    p = fma2(p, f, pk2(6.9314718056e-1f, 6.9314718056e-1f));
    p = fma2(p, f, pk2(1.0f, 1.0f));
    return mul2(p, sc);
}

// Software grid barrier. Monotonic epoch counters -> safe across graph replays.
__device__ __forceinline__ void gsync() {
    __syncthreads();
    if (threadIdx.x == 0) {
        __threadfence();
        unsigned t = atomicAdd(&g_arrive, 1u);
        unsigned ep = t / GRID + 1u;
        if (t % GRID == GRID - 1u) {
            g_release = ep;
        } else {
            while (g_release < ep) { __nanosleep(64); }
        }
        __threadfence();
    }
    __syncthreads();
}

__global__ void __launch_bounds__(TPB, 3) fkc_fused(
    const float* __restrict__ normals,
    const void*  __restrict__ nidx,
    const float* __restrict__ wa,
    const float* __restrict__ wb,
    const float* __restrict__ gamma,
    const float* __restrict__ beta,
    float* __restrict__ out)
{
    __shared__ float4 sWtmp[KK * 4];   // (wx*s, wy*s, wz*s, we) per (k, m)
    __shared__ float4 sW2[KK * 4];     // packed-pair layout (A, B, C, D per k)
    __shared__ int sIdx32;
    __shared__ unsigned sChunk;
    __shared__ float sh_s[8], sh_ss[8];

    int tid = threadIdx.x;
    const int lane = tid & 31;

    // Kernel-direction precompute (256 == KK*4 entries)
    {
        float a = wa[tid], b = wb[tid];
        float sa, ca, sb, cb;
        sincosf(a, &sa, &ca);
        sincosf(b, &sb, &cb);
        float wx = sa * cb, wy = sa * sb, wz = ca;
        float W2 = wx * wx + wy * wy + wz * wz;
        const float s = -2.0f * CLOG2;
        sWtmp[tid] = make_float4(wx * s, wy * s, wz * s, exp2f(CLOG2 * W2) * (1.0f / 16.0f));
    }
    if (tid == 0) {
        // Probe int32 (JAX default) vs int64 neighbor_idx
        int is32 = 0;
        const long long* p = (const long long*)nidx;
        for (int j = 0; j < 8; j++) {
            long long v = p[j];
            if (v < 0 || v >= NN) is32 = 1;
        }
        sIdx32 = is32;
    }
    if (blockIdx.x == 0 && tid < KK) { g_sum[tid] = 0.0; g_ssum[tid] = 0.0; }
    __syncthreads();

    // Repack per-k into m-pair layout for f32x2 math:
    //   A = (wx0, wx1, wy0, wy1)   B = (wz0, wz1, wx2, wx3)
    //   C = (wy2, wy3, wz2, wz3)   D = (we0, we1, we2, we3)
    {
        int k = tid >> 2, j = tid & 3;
        float4 W0 = sWtmp[4 * k + 0], W1 = sWtmp[4 * k + 1];
        float4 W2_ = sWtmp[4 * k + 2], W3 = sWtmp[4 * k + 3];
        float4 v;
        if (j == 0)      v = make_float4(W0.x, W1.x, W0.y, W1.y);
        else if (j == 1) v = make_float4(W0.z, W1.z, W2_.x, W3.x);
        else if (j == 2) v = make_float4(W2_.y, W3.y, W2_.z, W3.z);
        else             v = make_float4(W0.w, W1.w, W2_.w, W3.w);
        sW2[4 * k + j] = v;
    }
    __syncthreads();
    const int idx32 = sIdx32;

    // ---------------- Phase 1: compute feat (warp work-stealing) -----------
    for (;;) {
        unsigned u;
        if (lane == 0) u = atomicAdd(&g_work1, 1u);
        u = __shfl_sync(0xFFFFFFFFu, u, 0);
        if (u >= NUNIT) break;

        int pid = (int)u * PTS_W + lane;
        int b = pid >> 14;            // / NN
        int n = pid & (NN - 1);
        const float* nb = normals + (size_t)b * (3 * NN);

        int jj[4];
        jj[0] = n;
        if (idx32) {
            const int* ip = (const int*)nidx + ((size_t)b * NN + n) * 3;
            jj[1] = ip[0]; jj[2] = ip[1]; jj[3] = ip[2];
        } else {
            const long long* ip = (const long long*)nidx + ((size_t)b * NN + n) * 3;
            jj[1] = (int)ip[0]; jj[2] = (int)ip[1]; jj[3] = (int)ip[2];
        }

        // Broadcast-packed face-point coords and E factor
        u64 ffx[4], ffy[4], ffz[4], EE[4];
#pragma unroll
        for (int p = 0; p < 4; p++) {
            float x = __ldg(nb + jj[p]);
            float y = __ldg(nb + NN + jj[p]);
            float z = __ldg(nb + 2 * NN + jj[p]);
            float E = ex2f(CLOG2 * (x * x + y * y + z * z));
            ffx[p] = pk2(x, x);
            ffy[p] = pk2(y, y);
            ffz[p] = pk2(z, z);
            EE[p] = pk2(E, E);
        }

        float* op = out + (size_t)b * KK * NN + n;
#pragma unroll 2
        for (int k = 0; k < KK; k++) {
            float4 A = sW2[4 * k + 0];
            float4 B = sW2[4 * k + 1];
            float4 C = sW2[4 * k + 2];
            float4 D = sW2[4 * k + 3];
            u64 wx01 = pk2(A.x, A.y), wy01 = pk2(A.z, A.w), wz01 = pk2(B.x, B.y);
            u64 wx23 = pk2(B.z, B.w), wy23 = pk2(C.x, C.y), wz23 = pk2(C.z, C.w);
            u64 acc01 = 0ull, acc23 = 0ull;
#pragma unroll
            for (int p = 0; p < 4; p++) {
                u64 d01 = fma2(ffx[p], wx01, fma2(ffy[p], wy01, mul2(ffz[p], wz01)));
                u64 d23 = fma2(ffx[p], wx23, fma2(ffy[p], wy23, mul2(ffz[p], wz23)));
                float e0, e1;
                upk2(d01, e0, e1);
                u64 x01 = pk2(ex2f(e0), ex2f(e1));
                u64 x23;
                if (p & 1) {
                    // Offload 1/4 of exponentials to the FMA/ALU pipes
                    x23 = exp2poly2(d23);
                } else {
                    float e2, e3;
                    upk2(d23, e2, e3);
                    x23 = pk2(ex2f(e2), ex2f(e3));
                }
                acc01 = fma2(EE[p], x01, acc01);
                acc23 = fma2(EE[p], x23, acc23);
            }
            float a0, a1, a2, a3;
            upk2(acc01, a0, a1);
            upk2(acc23, a2, a3);
            op[(size_t)k * NN] = fmaf(a0, D.x, fmaf(a1, D.y, fmaf(a2, D.z, a3 * D.w)));
        }
    }

    gsync();   // all feat written, stats zeroed, g_work1 grabs done
    if (blockIdx.x == 0 && tid == 0) g_work1 = 0;   // reset for next replay

    // -------- Phase 2: per-(b,k) half-row sum / sumsq (L2-resident) --------
    for (;;) {
        if (tid == 0) sChunk = atomicAdd(&g_work2, 1u);
        __syncthreads();
        unsigned h = sChunk;
        __syncthreads();
        if (h >= NHALF) break;

        int r = (int)h >> 1;
        int k = r & (KK - 1);
        const float4* p4 = (const float4*)(out + (size_t)r * NN + (h & 1) * (NN / 2));
        float s = 0.f, ss = 0.f;
#pragma unroll
        for (int i = 0; i < NN / 8 / TPB; i++) {   // 8 iterations
            float4 v = p4[i * TPB + tid];
            s += (v.x + v.y) + (v.z + v.w);
            ss = fmaf(v.x, v.x, fmaf(v.y, v.y, fmaf(v.z, v.z, fmaf(v.w, v.w, ss))));
        }
#pragma unroll
        for (int o = 16; o; o >>= 1) {
            s  += __shfl_xor_sync(0xFFFFFFFFu, s, o);
            ss += __shfl_xor_sync(0xFFFFFFFFu, ss, o);
        }
        int w = tid >> 5, l = tid & 31;
        if (l == 0) { sh_s[w] = s; sh_ss[w] = ss; }
        __syncthreads();
        if (tid == 0) {
            float ts = 0.f, tss = 0.f;
#pragma unroll
            for (int i = 0; i < 8; i++) { ts += sh_s[i]; tss += sh_ss[i]; }
            atomicAdd(&g_sum[k],  (double)ts);
            atomicAdd(&g_ssum[k], (double)tss);
        }
        __syncthreads();
    }

    gsync();   // all stats accumulated
    if (blockIdx.x == 0 && tid == 0) g_work2 = 0;   // reset for next replay

    // ---------------- Phase 3: BN + ReLU in place (L2-resident) ------------
    for (int h = blockIdx.x; h < NHALF; h += GRID) {
        int r = h >> 1;
        int k = r & (KK - 1);
        double mean = g_sum[k] * (1.0 / MTOT);
        double var  = g_ssum[k] * (1.0 / MTOT) - mean * mean;
        float sc = __ldg(gamma + k) * rsqrtf((float)var + 1e-5f);
        float sh = __ldg(beta + k) - (float)mean * sc;
        float4* p4 = (float4*)(out + (size_t)r * NN + (h & 1) * (NN / 2));
#pragma unroll
        for (int i = 0; i < NN / 8 / TPB; i++) {   // 8 iterations
            float4 v = p4[i * TPB + tid];
            v.x = fmaxf(fmaf(v.x, sc, sh), 0.f);
            v.y = fmaxf(fmaf(v.y, sc, sh), 0.f);
            v.z = fmaxf(fmaf(v.z, sc, sh), 0.f);
            v.w = fmaxf(fmaf(v.w, sc, sh), 0.f);
            p4[i * TPB + tid] = v;
        }
    }
}

extern "C" void kernel_launch(void* const* d_in, const int* in_sizes, int n_in,
                              void* d_out, int out_size) {
    const float* normals = (const float*)d_in[0];
    const void*  nidx    = d_in[1];
    const float* wa      = (const float*)d_in[2];
    const float* wb      = (const float*)d_in[3];
    const float* gamma   = (const float*)d_in[4];
    const float* beta    = (const float*)d_in[5];
    float* out = (float*)d_out;

    fkc_fused<<<GRID, TPB>>>(normals, nidx, wa, wb, gamma, beta, out);
}

// round 17
// speedup vs baseline: 1.9596x; 1.1967x over previous
#include <cuda_runtime.h>

// Problem constants (fixed by setup_inputs): B=8, N=16384, K=64
#define BB    8
#define NN    16384
#define KK    64
#define MTOT  (BB * NN)            // 131072 points total
#define NROWS (BB * KK)            // 512 (b,k) rows
#define NHALF (NROWS * 2)          // 1024 half-row BN units
// inv = -1/(2*sigma^2) = -12.5 ;  C = inv * log2(e)
#define CLOG2 (-18.033688011112043f)

#define GRID  444                  // 3 CTAs/SM on 148 SMs, all co-resident
#define TPB   256                  // 8 warps
#define PTS_A 32
#define NUNITA (MTOT / PTS_A)      // 4096 stage-A warp units
#define PTS_B 16
#define NUNITB (MTOT / PTS_B)      // 8192 stage-B warp units

// Scratch (no cudaMalloc allowed)
__device__ float  g_h[(size_t)MTOT * KK];   // 33.5 MB: h[b][j][k], k contiguous
__device__ double g_sum[KK];
__device__ double g_ssum[KK];
__device__ unsigned g_workA;
__device__ unsigned g_workB;
__device__ unsigned g_arrive;               // grid barrier, monotonic across replays
__device__ volatile unsigned g_release;

__device__ __forceinline__ float ex2f(float x) {
    float r;
    asm("ex2.approx.ftz.f32 %0, %1;" : "=f"(r) : "f"(x));
    return r;
}

// Software grid barrier. Monotonic epoch counters -> safe across graph replays.
__device__ __forceinline__ void gsync() {
    __syncthreads();
    if (threadIdx.x == 0) {
        __threadfence();
        unsigned t = atomicAdd(&g_arrive, 1u);
        unsigned ep = t / GRID + 1u;
        if (t % GRID == GRID - 1u) {
            g_release = ep;
        } else {
            while (g_release < ep) { __nanosleep(64); }
        }
        __threadfence();
    }
    __syncthreads();
}

__global__ void __launch_bounds__(TPB, 3) fkc_fused(
    const float* __restrict__ normals,
    const void*  __restrict__ nidx,
    const float* __restrict__ wa,
    const float* __restrict__ wb,
    const float* __restrict__ gamma,
    const float* __restrict__ beta,
    float* __restrict__ out)
{
    __shared__ float sT[8][PTS_B * 65];     // per-warp transpose tiles (33.3 KB)
    __shared__ float sS[8][16][4];          // per-warp stats staging
    __shared__ float sQ[8][16][4];
    __shared__ int   sIdx32;

    const int tid  = threadIdx.x;
    const int warp = tid >> 5;
    const int lane = tid & 31;
    float* sTw = sT[warp];

    if (tid == 0) {
        // Probe int32 (JAX default) vs int64 neighbor_idx
        int is32 = 0;
        const long long* p = (const long long*)nidx;
        for (int j = 0; j < 8; j++) {
            long long v = p[j];
            if (v < 0 || v >= NN) is32 = 1;
        }
        sIdx32 = is32;
    }
    if (blockIdx.x == 0 && tid < KK) { g_sum[tid] = 0.0; g_ssum[tid] = 0.0; }

    // Per-lane weights: k = lane (low half) and k = lane+32 (high half)
    // w' = -2C * w ; we = exp2(C*||w||^2)/16
    float WxL[4], WyL[4], WzL[4], WeL[4];
    float WxH[4], WyH[4], WzH[4], WeH[4];
#pragma unroll
    for (int m = 0; m < 4; m++) {
#pragma unroll
        for (int half = 0; half < 2; half++) {
            int k = lane + half * 32;
            float a = __ldg(wa + k * 4 + m), b = __ldg(wb + k * 4 + m);
            float sa, ca, sb, cb;
            sincosf(a, &sa, &ca);
            sincosf(b, &sb, &cb);
            float wx = sa * cb, wy = sa * sb, wz = ca;
            float W2 = wx * wx + wy * wy + wz * wz;
            const float s = -2.0f * CLOG2;
            float we = exp2f(CLOG2 * W2) * (1.0f / 16.0f);
            if (half == 0) { WxL[m] = wx * s; WyL[m] = wy * s; WzL[m] = wz * s; WeL[m] = we; }
            else           { WxH[m] = wx * s; WyH[m] = wy * s; WzH[m] = wz * s; WeH[m] = we; }
        }
    }
    __syncthreads();
    const int idx32 = sIdx32;

    // ---- Stage A: h[b][j][k] = sum_m exp2(f.w'_km + C||f||^2) * we_km ----
    // Warp-autonomous; lane = channel k / k+32; writes 256B-coalesced rows.
    for (;;) {
        unsigned u;
        if (lane == 0) u = atomicAdd(&g_workA, 1u);
        u = __shfl_sync(0xFFFFFFFFu, u, 0);
        if (u >= NUNITA) break;

        int base = (int)u * PTS_A;
        int b  = base >> 14;
        int n0 = base & (NN - 1);
        const float* nb = normals + (size_t)b * (3 * NN);
        float* hp = g_h + ((size_t)b * NN + n0) * KK + lane;

#pragma unroll 4
        for (int p = 0; p < PTS_A; p++) {
            int n = n0 + p;
            float x = __ldg(nb + n);
            float y = __ldg(nb + NN + n);
            float z = __ldg(nb + 2 * NN + n);
            float cf2 = CLOG2 * fmaf(x, x, fmaf(y, y, z * z));
            float slo = 0.f, shi = 0.f;
#pragma unroll
            for (int m = 0; m < 4; m++) {
                slo = fmaf(ex2f(fmaf(x, WxL[m], fmaf(y, WyL[m], fmaf(z, WzL[m], cf2)))), WeL[m], slo);
                shi = fmaf(ex2f(fmaf(x, WxH[m], fmaf(y, WyH[m], fmaf(z, WzH[m], cf2)))), WeH[m], shi);
            }
            hp[(size_t)p * KK]      = slo;
            hp[(size_t)p * KK + 32] = shi;
        }
    }

    gsync();   // all h written, stats zeroed
    if (blockIdx.x == 0 && tid == 0) g_workA = 0;   // reset for next replay

    // ---- Stage B: feat[n][k] = h[n][k]+h[j1][k]+h[j2][k]+h[j3][k] --------
    // lane = (pt-half hh, k-quad qd); 4 indep LDG.128 per step; fixed channels
    // per thread -> stats in registers; per-warp smem tile, __syncwarp only.
    const int qd   = lane & 15;        // k-quad: channels 4*qd .. 4*qd+3 (fixed)
    const int hh   = lane >> 4;        // which of the 2 points in a step
    const int coff = qd * 4;
    float4 s4 = make_float4(0.f, 0.f, 0.f, 0.f);
    float4 q4 = make_float4(0.f, 0.f, 0.f, 0.f);

    for (;;) {
        unsigned u;
        if (lane == 0) u = atomicAdd(&g_workB, 1u);
        u = __shfl_sync(0xFFFFFFFFu, u, 0);
        if (u >= NUNITB) break;

        int base = (int)u * PTS_B;
        int b  = base >> 14;
        int n0 = base & (NN - 1);
        const float* hb = g_h + (size_t)b * NN * KK;

#pragma unroll 2
        for (int i = 0; i < PTS_B / 2; i++) {
            int p = 2 * i + hh;
            int n = n0 + p;
            int j1, j2, j3;
            {
                size_t rowbase = ((size_t)b * NN + n) * 3;
                if (idx32) {
                    const int* ip = (const int*)nidx + rowbase;
                    j1 = ip[0]; j2 = ip[1]; j3 = ip[2];
                } else {
                    const long long* ip = (const long long*)nidx + rowbase;
                    j1 = (int)ip[0]; j2 = (int)ip[1]; j3 = (int)ip[2];
                }
            }
            float4 v0 = __ldg((const float4*)(hb + (size_t)n  * KK + coff));
            float4 v1 = __ldg((const float4*)(hb + (size_t)j1 * KK + coff));
            float4 v2 = __ldg((const float4*)(hb + (size_t)j2 * KK + coff));
            float4 v3 = __ldg((const float4*)(hb + (size_t)j3 * KK + coff));
            float4 v;
            v.x = (v0.x + v1.x) + (v2.x + v3.x);
            v.y = (v0.y + v1.y) + (v2.y + v3.y);
            v.z = (v0.z + v1.z) + (v2.z + v3.z);
            v.w = (v0.w + v1.w) + (v2.w + v3.w);
            float* tp = sTw + p * 65 + coff;
            tp[0] = v.x; tp[1] = v.y; tp[2] = v.z; tp[3] = v.w;
            s4.x += v.x; s4.y += v.y; s4.z += v.z; s4.w += v.w;
            q4.x = fmaf(v.x, v.x, q4.x); q4.y = fmaf(v.y, v.y, q4.y);
            q4.z = fmaf(v.z, v.z, q4.z); q4.w = fmaf(v.w, v.w, q4.w);
        }
        __syncwarp();

        // Transposed flush: half-warps write rows 2*ki+hh; 16 consecutive n
        // per row = 64B-coalesced stores. Bank-conflict-free via stride 65.
        {
            float* ob = out + (size_t)b * KK * NN + n0 + qd;
#pragma unroll 8
            for (int ki = 0; ki < KK / 2; ki++) {
                int k2 = 2 * ki + hh;
                ob[(size_t)k2 * NN] = sTw[qd * 65 + k2];
            }
        }
        __syncwarp();
    }

    // Stats: pair lanes (qd, qd+16) share channels -> shfl reduce, stage, sum
    s4.x += __shfl_xor_sync(0xFFFFFFFFu, s4.x, 16);
    s4.y += __shfl_xor_sync(0xFFFFFFFFu, s4.y, 16);
    s4.z += __shfl_xor_sync(0xFFFFFFFFu, s4.z, 16);
    s4.w += __shfl_xor_sync(0xFFFFFFFFu, s4.w, 16);
    q4.x += __shfl_xor_sync(0xFFFFFFFFu, q4.x, 16);
    q4.y += __shfl_xor_sync(0xFFFFFFFFu, q4.y, 16);
    q4.z += __shfl_xor_sync(0xFFFFFFFFu, q4.z, 16);
    q4.w += __shfl_xor_sync(0xFFFFFFFFu, q4.w, 16);
    if (lane < 16) {
        sS[warp][lane][0] = s4.x; sS[warp][lane][1] = s4.y;
        sS[warp][lane][2] = s4.z; sS[warp][lane][3] = s4.w;
        sQ[warp][lane][0] = q4.x; sQ[warp][lane][1] = q4.y;
        sQ[warp][lane][2] = q4.z; sQ[warp][lane][3] = q4.w;
    }
    __syncthreads();
    if (tid < KK) {
        int q = tid >> 2, c = tid & 3;
        float ts = 0.f, tss = 0.f;
#pragma unroll
        for (int w = 0; w < 8; w++) { ts += sS[w][q][c]; tss += sQ[w][q][c]; }
        atomicAdd(&g_sum[tid],  (double)ts);
        atomicAdd(&g_ssum[tid], (double)tss);
    }

    gsync();   // all stats accumulated, all feat rows written
    if (blockIdx.x == 0 && tid == 0) g_workB = 0;   // reset for next replay

    // ---- Stage C: BN + ReLU in place (L2-resident) ------------------------
    for (int h = blockIdx.x; h < NHALF; h += GRID) {
        int r = h >> 1;
        int kk = r & (KK - 1);
        double mean = g_sum[kk] * (1.0 / MTOT);
        double var  = g_ssum[kk] * (1.0 / MTOT) - mean * mean;
        float sc = __ldg(gamma + kk) * rsqrtf((float)var + 1e-5f);
        float sh = __ldg(beta + kk) - (float)mean * sc;
        float4* p4 = (float4*)(out + (size_t)r * NN + (h & 1) * (NN / 2));
#pragma unroll
        for (int i = 0; i < NN / 8 / TPB; i++) {   // 8 iterations
            float4 v = p4[i * TPB + tid];
            v.x = fmaxf(fmaf(v.x, sc, sh), 0.f);
            v.y = fmaxf(fmaf(v.y, sc, sh), 0.f);
            v.z = fmaxf(fmaf(v.z, sc, sh), 0.f);
            v.w = fmaxf(fmaf(v.w, sc, sh), 0.f);
            p4[i * TPB + tid] = v;
        }
    }
}

extern "C" void kernel_launch(void* const* d_in, const int* in_sizes, int n_in,
                              void* d_out, int out_size) {
    const float* normals = (const float*)d_in[0];
    const void*  nidx    = d_in[1];
    const float* wa      = (const float*)d_in[2];
    const float* wb      = (const float*)d_in[3];
    const float* gamma   = (const float*)d_in[4];
    const float* beta    = (const float*)d_in[5];
    float* out = (float*)d_out;

    fkc_fused<<<GRID, TPB>>>(normals, nidx, wa, wb, gamma, beta, out);
}